// round 9
// baseline (speedup 1.0000x reference)
#include <cuda_runtime.h>
#include <cuda_bf16.h>

// ---------------------------------------------------------------------------
// LoongSpikeKernel: K[ch,h,l] = 2*Re( sum_n C_disc[h,n] * exp(dtA[h,n]*l) )
// H=512, NS=64 states/h, L=2048, CH=1.
//
// R9: single-wave geometry. R8 was 2 waves (512 CTAs over 444 slots, wave 2
//     only 15% full). Repartition: 8 states/thread (NP=4), 32 l-lanes,
//     8 groups (warp==group), stride-32 recurrence r32=exp(32*dtA), 64 k's.
//     Regs ~55 -> __launch_bounds__(256,4) -> 592 slots >= 512 CTAs = 1 wave.
//     Loop FLOPs / seed count / banking cost per step all unchanged.
// ---------------------------------------------------------------------------

#define NS 64   // states per h (M*NST)
#define GS 8    // states per thread
#define NP 4    // packed state-pairs per thread
#define NLANE 32
#define KCH 32  // k-iters buffered in smem per chunk

typedef unsigned long long ull;

// Scratch (device globals; allocation-free rule)
__device__ float2 g_dtA[512 * NS];
__device__ float2 g_C2 [512 * NS];
__device__ float4 g_R32[512 * NS];   // (rr, ri, 2*rr, -|r32|^2), r32 = exp(32*dtA)

// fp32 two-term Cody-Waite reduction + fast sincos.
__device__ __forceinline__ void sincos_cw(float x, float* s, float* c) {
    float k = rintf(x * 0.15915494309189535f);
    float r = fmaf(k, -6.28125f, x);
    r = fmaf(k, -1.9353071795864769e-3f, r);
    __sincosf(r, s, c);
}

__device__ __forceinline__ ull pack2(float lo, float hi) {
    ull r;
    asm("mov.b64 %0, {%1, %2};" : "=l"(r)
        : "r"(__float_as_uint(lo)), "r"(__float_as_uint(hi)));
    return r;
}
__device__ __forceinline__ ull add2(ull a, ull b) {
    ull r; asm("add.rn.f32x2 %0, %1, %2;" : "=l"(r) : "l"(a), "l"(b)); return r;
}
__device__ __forceinline__ ull mul2(ull a, ull b) {
    ull r; asm("mul.rn.f32x2 %0, %1, %2;" : "=l"(r) : "l"(a), "l"(b)); return r;
}
__device__ __forceinline__ ull fma2(ull a, ull b, ull c) {
    ull r; asm("fma.rn.f32x2 %0, %1, %2, %3;" : "=l"(r) : "l"(a), "l"(b), "l"(c)); return r;
}
__device__ __forceinline__ float sum2(ull a) {
    unsigned lo, hi;
    asm("mov.b64 {%0, %1}, %2;" : "=r"(lo), "=r"(hi) : "l"(a));
    return __uint_as_float(lo) + __uint_as_float(hi);
}

// ---------------------------------------------------------------------------
__global__ void loong_pre(const float* __restrict__ C_real,
                          const float* __restrict__ log_dt,
                          const float* __restrict__ log_A_real,
                          const float* __restrict__ A_imag,
                          const float* __restrict__ omega_logit,
                          const float* __restrict__ eta_logit,
                          int H, int NST, int M) {
    const float OMIN = 1e-6f, OMAX = 100.0f, EMIN = 1e-6f, EMAX = 10.0f;
    int idx = blockIdx.x * blockDim.x + threadIdx.x;
    int total = H * M * NST;
    if (idx >= total) return;
    int h = idx / (M * NST);
    int j = idx - h * (M * NST);
    int m = j / NST;
    int n = j - m * NST;

    float dt    = expf(log_dt[h]);
    float omega = OMIN + (OMAX - OMIN) / (1.f + expf(-omega_logit[m]));
    float eta   = EMIN + (EMAX - EMIN) / (1.f + expf(-eta_logit[m]));
    float Are   = -expf(log_A_real[h * NST + n]);
    float Aim   = A_imag[h * NST + n];
    float Afr   = -omega + eta * Are;
    float Afi   = eta * Aim;
    float Cr    = eta * C_real[(h * NST + n) * 2 + 0];   // CH = 1
    float Ci    = eta * C_real[(h * NST + n) * 2 + 1];
    float dtAr  = Afr * dt;
    float dtAi  = Afi * dt;

    // (exp(dtA) - 1) / (A_frac + 1e-8)
    float er = expf(dtAr);
    float s1, c1; sincos_cw(dtAi, &s1, &c1);
    float nr = er * c1 - 1.f;
    float ni = er * s1;
    float dr  = Afr + 1e-8f, di = Afi;
    float inv = 1.f / (dr * dr + di * di);
    float qr  = (nr * dr + ni * di) * inv;
    float qi  = (ni * dr - nr * di) * inv;
    float Cdr = Cr * qr - Ci * qi;
    float Cdi = Cr * qi + Ci * qr;
    if (sqrtf(Afr * Afr + Afi * Afi) < 1e-6f) { Cdr = Cr * dt; Cdi = Ci * dt; }

    g_dtA[idx] = make_float2(dtAr, dtAi);
    g_C2 [idx] = make_float2(2.f * Cdr, 2.f * Cdi);

    // r32 = exp(32*dtA); recurrence constants: twoa = 2*Re(r32), negq = -|r32|^2
    float e32 = expf(32.f * dtAr);
    float s32, c32; sincos_cw(32.f * dtAi, &s32, &c32);
    float rr = e32 * c32, ri = e32 * s32;
    float negq = -expf(64.f * dtAr);         // -(e32^2), computed exactly
    g_R32[idx] = make_float4(rr, ri, 2.f * rr, negq);
}

// ---------------------------------------------------------------------------
__global__ __launch_bounds__(256, 4) void loong_main(float* __restrict__ out, int L) {
    const int h    = blockIdx.x;
    const int tid  = threadIdx.x;
    const int g    = tid >> 5;     // state group 0..7 (== warp id)
    const int t    = tid & 31;     // l lane 0..31
    const int base = h * NS + g * GS;

    const int iters = (L + NLANE - 1) / NLANE;    // total k's (64)

    // --- seed: A = s(t), B = s(t+32) for 8 states, packed as 4 pairs ---
    ull A[NP], B[NP], twoa[NP], negq[NP];
    const float tf = (float)t;
    // Re(dtA) is identical across this thread's states (same h, same m):
    const float E = __expf(g_dtA[base].x * tf);
#pragma unroll
    for (int p = 0; p < NP; p++) {
        float s0v[2], s1v[2], tw[2], nq[2];
#pragma unroll
        for (int e = 0; e < 2; e++) {
            int i = base + 2 * p + e;
            float2 a = g_dtA[i];
            float2 c = g_C2 [i];
            float4 q = g_R32[i];
            float s, co; sincos_cw(a.y * tf, &s, &co);   // per-state exact phase
            float xr = E * co, xi = E * s;
            float wr = c.x * xr - c.y * xi;      // Re(C2 * e^{dtA t})
            float wi = c.x * xi + c.y * xr;
            s0v[e] = wr;
            s1v[e] = wr * q.x - wi * q.y;        // Re(w * r32)
            tw[e]  = q.z;
            nq[e]  = q.w;
        }
        A[p]    = pack2(s0v[0], s0v[1]);
        B[p]    = pack2(s1v[0], s1v[1]);
        twoa[p] = pack2(tw[0],  tw[1]);
        negq[p] = pack2(nq[0],  nq[1]);
    }

    __shared__ float sR[KCH][8][NLANE];       // per-k group partials (32 KB)
    const long long ob = (long long)h * L;

    for (int kk0 = 0; kk0 < iters; kk0 += KCH) {
        const int kend = (iters - kk0 < KCH) ? (iters - kk0) : KCH;
#pragma unroll 1
        for (int k = 0; k < kend; k += 2) {
            // --- step even: output A, advance A <- twoa*B + negq*A ---
            {
                ull a0 = 0ull, a1 = 0ull, a2 = 0ull, a3 = 0ull;
                a0 = add2(a0, A[0]);
                a1 = add2(a1, A[1]);
                a2 = add2(a2, A[2]);
                a3 = add2(a3, A[3]);
#pragma unroll
                for (int p = 0; p < NP; p++)
                    A[p] = fma2(B[p], twoa[p], mul2(A[p], negq[p]));
                sR[k][g][t] = sum2(add2(add2(a0, a1), add2(a2, a3)));
            }
            // --- step odd: output B, advance B <- twoa*A + negq*B ---
            {
                ull a0 = 0ull, a1 = 0ull, a2 = 0ull, a3 = 0ull;
                a0 = add2(a0, B[0]);
                a1 = add2(a1, B[1]);
                a2 = add2(a2, B[2]);
                a3 = add2(a3, B[3]);
#pragma unroll
                for (int p = 0; p < NP; p++)
                    B[p] = fma2(A[p], twoa[p], mul2(B[p], negq[p]));
                sR[k + 1][g][t] = sum2(add2(add2(a0, a1), add2(a2, a3)));
            }
        }
        __syncthreads();
        // coalesced epilogue: sum the 8 group partials
        const int lbeg = kk0 * NLANE;
        const int lend = lbeg + kend * NLANE;
        for (int l = lbeg + tid; l < lend && l < L; l += 256) {
            int kk = (l >> 5) - kk0, tt = l & 31;
            out[ob + l] = ((sR[kk][0][tt] + sR[kk][1][tt])
                         + (sR[kk][2][tt] + sR[kk][3][tt]))
                        + ((sR[kk][4][tt] + sR[kk][5][tt])
                         + (sR[kk][6][tt] + sR[kk][7][tt]));
        }
        __syncthreads();
    }
}

// ---------------------------------------------------------------------------
extern "C" void kernel_launch(void* const* d_in, const int* in_sizes, int n_in,
                              void* d_out, int out_size) {
    const float* C_real      = (const float*)d_in[0];
    const float* log_dt      = (const float*)d_in[1];
    const float* log_A_real  = (const float*)d_in[2];
    const float* A_imag      = (const float*)d_in[3];
    const float* omega_logit = (const float*)d_in[4];
    const float* eta_logit   = (const float*)d_in[5];

    int H   = in_sizes[1];               // 512
    int NST = in_sizes[2] / H;           // 32
    int M   = in_sizes[4];               // 2
    int L   = out_size / H;              // 2048 (CH = 1)

    int total = H * M * NST;
    loong_pre<<<(total + 127) / 128, 128>>>(C_real, log_dt, log_A_real, A_imag,
                                            omega_logit, eta_logit, H, NST, M);
    loong_main<<<H, 256>>>((float*)d_out, L);
}

// round 10
// speedup vs baseline: 1.1473x; 1.1473x over previous
#include <cuda_runtime.h>
#include <cuda_bf16.h>

// ---------------------------------------------------------------------------
// LoongSpikeKernel: K[ch,h,l] = 2*Re( sum_n C_disc[h,n] * exp(dtA[h,n]*l) )
// H=512, NS=64 states/h, L=2048, CH=1.
//
// R10 (on R9's single-wave stride-32 2nd-order real recurrence):
//  - FUSED: the parameter->constant computation (old pre-kernel) now runs in
//    each CTA's first 64 threads into smem. One launch total (-~2.9us).
//  - Tree-sum fix: 3 add2 per half-step instead of 7 (R9 issued 4 dead
//    copies per k through asm accumulator-init) -> inner loop 34->26
//    banking cycles per k.
//  - Geometry: 256 thr (8 warps = 8 state-groups x 32 lanes), NP=4 pairs,
//    <=64 regs, 4 CTAs/SM, grid=512 -> one wave.
// ---------------------------------------------------------------------------

#define NS 64   // states per h (M*NST)
#define GS 8    // states per thread
#define NP 4    // packed state-pairs per thread
#define NLANE 32
#define KCH 32  // k-iters buffered in smem per chunk

typedef unsigned long long ull;

// fp32 two-term Cody-Waite reduction + fast sincos.
__device__ __forceinline__ void sincos_cw(float x, float* s, float* c) {
    float k = rintf(x * 0.15915494309189535f);
    float r = fmaf(k, -6.28125f, x);
    r = fmaf(k, -1.9353071795864769e-3f, r);
    __sincosf(r, s, c);
}

__device__ __forceinline__ ull pack2(float lo, float hi) {
    ull r;
    asm("mov.b64 %0, {%1, %2};" : "=l"(r)
        : "r"(__float_as_uint(lo)), "r"(__float_as_uint(hi)));
    return r;
}
__device__ __forceinline__ ull add2(ull a, ull b) {
    ull r; asm("add.rn.f32x2 %0, %1, %2;" : "=l"(r) : "l"(a), "l"(b)); return r;
}
__device__ __forceinline__ ull mul2(ull a, ull b) {
    ull r; asm("mul.rn.f32x2 %0, %1, %2;" : "=l"(r) : "l"(a), "l"(b)); return r;
}
__device__ __forceinline__ ull fma2(ull a, ull b, ull c) {
    ull r; asm("fma.rn.f32x2 %0, %1, %2, %3;" : "=l"(r) : "l"(a), "l"(b), "l"(c)); return r;
}
__device__ __forceinline__ float sum2(ull a) {
    unsigned lo, hi;
    asm("mov.b64 {%0, %1}, %2;" : "=r"(lo), "=r"(hi) : "l"(a));
    return __uint_as_float(lo) + __uint_as_float(hi);
}

// ---------------------------------------------------------------------------
__global__ __launch_bounds__(256, 4) void loong_fused(
    float* __restrict__ out,
    const float* __restrict__ C_real,
    const float* __restrict__ log_dt,
    const float* __restrict__ log_A_real,
    const float* __restrict__ A_imag,
    const float* __restrict__ omega_logit,
    const float* __restrict__ eta_logit,
    int NST, int L) {
    const float OMIN = 1e-6f, OMAX = 100.0f, EMIN = 1e-6f, EMAX = 10.0f;
    const int h    = blockIdx.x;
    const int tid  = threadIdx.x;
    const int g    = tid >> 5;     // state group 0..7 (== warp id)
    const int t    = tid & 31;     // l lane 0..31

    __shared__ float2 s_dtA[NS];
    __shared__ float2 s_C2 [NS];
    __shared__ float4 s_R32[NS];              // (rr, ri, 2*rr, -|r32|^2)
    __shared__ float  sR[KCH][8][NLANE];      // per-k group partials (32 KB)

    // ---- phase 0: per-CTA constants (old pre-kernel), 64 threads ----
    if (tid < NS) {
        int m = tid / NST;                    // 0..M-1
        int n = tid - m * NST;                // 0..NST-1
        int gi = h * NST + n;

        float dt    = expf(log_dt[h]);
        float omega = OMIN + (OMAX - OMIN) / (1.f + expf(-omega_logit[m]));
        float eta   = EMIN + (EMAX - EMIN) / (1.f + expf(-eta_logit[m]));
        float Are   = -expf(log_A_real[gi]);
        float Aim   = A_imag[gi];
        float Afr   = -omega + eta * Are;
        float Afi   = eta * Aim;
        float Cr    = eta * C_real[gi * 2 + 0];   // CH = 1
        float Ci    = eta * C_real[gi * 2 + 1];
        float dtAr  = Afr * dt;
        float dtAi  = Afi * dt;

        // (exp(dtA) - 1) / (A_frac + 1e-8)
        float er = expf(dtAr);
        float s1, c1; sincos_cw(dtAi, &s1, &c1);
        float nr = er * c1 - 1.f;
        float ni = er * s1;
        float dr  = Afr + 1e-8f, di = Afi;
        float inv = 1.f / (dr * dr + di * di);
        float qr  = (nr * dr + ni * di) * inv;
        float qi  = (ni * dr - nr * di) * inv;
        float Cdr = Cr * qr - Ci * qi;
        float Cdi = Cr * qi + Ci * qr;
        if (sqrtf(Afr * Afr + Afi * Afi) < 1e-6f) { Cdr = Cr * dt; Cdi = Ci * dt; }

        s_dtA[tid] = make_float2(dtAr, dtAi);
        s_C2 [tid] = make_float2(2.f * Cdr, 2.f * Cdi);

        // r32 = exp(32*dtA); twoa = 2*Re(r32), negq = -|r32|^2
        float e32 = expf(32.f * dtAr);
        float s32, c32; sincos_cw(32.f * dtAi, &s32, &c32);
        float rr = e32 * c32, ri = e32 * s32;
        float negq = -expf(64.f * dtAr);
        s_R32[tid] = make_float4(rr, ri, 2.f * rr, negq);
    }
    __syncthreads();

    // ---- phase 1: seed A = s(t), B = s(t+32) for 8 states (4 pairs) ----
    const int base = g * GS;
    ull A[NP], B[NP], twoa[NP], negq[NP];
    const float tf = (float)t;
    // Re(dtA) identical across this thread's 8 states (same h, same m):
    const float E = __expf(s_dtA[base].x * tf);
#pragma unroll
    for (int p = 0; p < NP; p++) {
        float s0v[2], s1v[2], tw[2], nq[2];
#pragma unroll
        for (int e = 0; e < 2; e++) {
            int i = base + 2 * p + e;
            float2 a = s_dtA[i];
            float2 c = s_C2 [i];
            float4 q = s_R32[i];
            float s, co; sincos_cw(a.y * tf, &s, &co);   // per-state exact phase
            float xr = E * co, xi = E * s;
            float wr = c.x * xr - c.y * xi;      // Re(C2 * e^{dtA t})
            float wi = c.x * xi + c.y * xr;
            s0v[e] = wr;
            s1v[e] = wr * q.x - wi * q.y;        // Re(w * r32)
            tw[e]  = q.z;
            nq[e]  = q.w;
        }
        A[p]    = pack2(s0v[0], s0v[1]);
        B[p]    = pack2(s1v[0], s1v[1]);
        twoa[p] = pack2(tw[0],  tw[1]);
        negq[p] = pack2(nq[0],  nq[1]);
    }

    const int iters = (L + NLANE - 1) / NLANE;    // total k's (64)
    const long long ob = (long long)h * L;

    // ---- phase 2: recurrence ----
    for (int kk0 = 0; kk0 < iters; kk0 += KCH) {
        const int kend = (iters - kk0 < KCH) ? (iters - kk0) : KCH;
#pragma unroll 1
        for (int k = 0; k < kend; k += 2) {
            // step even: output sum(A), advance A <- twoa*B + negq*A
            {
                ull t01 = add2(A[0], A[1]);
                ull t23 = add2(A[2], A[3]);
#pragma unroll
                for (int p = 0; p < NP; p++)
                    A[p] = fma2(B[p], twoa[p], mul2(A[p], negq[p]));
                sR[k][g][t] = sum2(add2(t01, t23));
            }
            // step odd: output sum(B), advance B <- twoa*A + negq*B
            {
                ull t01 = add2(B[0], B[1]);
                ull t23 = add2(B[2], B[3]);
#pragma unroll
                for (int p = 0; p < NP; p++)
                    B[p] = fma2(A[p], twoa[p], mul2(B[p], negq[p]));
                sR[k + 1][g][t] = sum2(add2(t01, t23));
            }
        }
        __syncthreads();
        // coalesced epilogue: sum the 8 group partials
        const int lbeg = kk0 * NLANE;
        const int lend = lbeg + kend * NLANE;
        for (int l = lbeg + tid; l < lend && l < L; l += 256) {
            int kk = (l >> 5) - kk0, tt = l & 31;
            out[ob + l] = ((sR[kk][0][tt] + sR[kk][1][tt])
                         + (sR[kk][2][tt] + sR[kk][3][tt]))
                        + ((sR[kk][4][tt] + sR[kk][5][tt])
                         + (sR[kk][6][tt] + sR[kk][7][tt]));
        }
        __syncthreads();
    }
}

// ---------------------------------------------------------------------------
extern "C" void kernel_launch(void* const* d_in, const int* in_sizes, int n_in,
                              void* d_out, int out_size) {
    const float* C_real      = (const float*)d_in[0];
    const float* log_dt      = (const float*)d_in[1];
    const float* log_A_real  = (const float*)d_in[2];
    const float* A_imag      = (const float*)d_in[3];
    const float* omega_logit = (const float*)d_in[4];
    const float* eta_logit   = (const float*)d_in[5];

    int H   = in_sizes[1];               // 512
    int NST = in_sizes[2] / H;           // 32
    int L   = out_size / H;              // 2048 (CH = 1)

    loong_fused<<<H, 256>>>((float*)d_out, C_real, log_dt, log_A_real,
                            A_imag, omega_logit, eta_logit, NST, L);
}